// round 2
// baseline (speedup 1.0000x reference)
#include <cuda_runtime.h>
#include <math.h>

// Problem constants
#define BB   2
#define NN   2048
#define EE   1024
#define HH   8
#define DDIM 64          // half-head dim
#define VDIM 128         // 2*D, v head dim
#define DEPTH_C 12
#define LN_EPS 1e-5f

// ---------------------------------------------------------------------------
// Device scratch (static — no allocations allowed)
// ---------------------------------------------------------------------------
__device__ float g_Q[(size_t)BB * NN * EE];
__device__ float g_K[(size_t)BB * NN * EE];
__device__ float g_V[(size_t)BB * NN * EE];
__device__ float g_ATT[(size_t)BB * NN * EE];
__device__ float g_lambda;

// ---------------------------------------------------------------------------
// Lambda scalar kernel
// ---------------------------------------------------------------------------
__global__ void lambda_kernel(const float* __restrict__ lq1,
                              const float* __restrict__ lk1,
                              const float* __restrict__ lq2,
                              const float* __restrict__ lk2) {
    int lane = threadIdx.x;
    float s1 = 0.f, s2 = 0.f;
    for (int i = lane; i < DDIM; i += 32) {
        s1 += lq1[i] * lk1[i];
        s2 += lq2[i] * lk2[i];
    }
    #pragma unroll
    for (int off = 16; off; off >>= 1) {
        s1 += __shfl_xor_sync(0xFFFFFFFFu, s1, off);
        s2 += __shfl_xor_sync(0xFFFFFFFFu, s2, off);
    }
    if (lane == 0) {
        float lam_init = 0.8f - 0.6f * expf(-0.3f * (float)DEPTH_C);
        g_lambda = expf(s1) - expf(s2) + lam_init;
    }
}

// ---------------------------------------------------------------------------
// SGEMM: C[M,N] = alpha * A[M,K] @ B[K,N]  (row-major)
// 128x128 block tile, BK=8, 256 threads, 8x8 per thread (4x4 quadrants).
// ---------------------------------------------------------------------------
#define BM 128
#define BN 128
#define BKK 8

__global__ void __launch_bounds__(256)
sgemm128(const float* __restrict__ A, const float* __restrict__ B,
         float* __restrict__ C, int M, int N, int K, float alpha) {
    __shared__ __align__(16) float As[BKK][BM + 4];  // [k][m], padded (conflict-free store)
    __shared__ __align__(16) float Bs[BKK][BN];      // [k][n]

    const int tid = threadIdx.x;
    const int tx = tid & 15;          // 0..15
    const int ty = tid >> 4;          // 0..15
    const int row0 = blockIdx.y * BM;
    const int col0 = blockIdx.x * BN;

    // A tile: 128 rows x 8 cols = 256 float4; thread t: row t/2, col (t&1)*4
    const int ar = tid >> 1;
    const int ac = (tid & 1) * 4;
    // B tile: 8 rows x 128 cols = 256 float4; thread t: row t/32, col (t&31)*4
    const int br = tid >> 5;
    const int bc = (tid & 31) * 4;

    float acc[8][8];
    #pragma unroll
    for (int i = 0; i < 8; i++)
        #pragma unroll
        for (int j = 0; j < 8; j++) acc[i][j] = 0.f;

    const float* Aptr = A + (size_t)(row0 + ar) * K + ac;
    const float* Bptr = B + (size_t)br * N + col0 + bc;

    for (int k0 = 0; k0 < K; k0 += BKK) {
        float4 av = *(const float4*)(Aptr + k0);
        As[ac + 0][ar] = av.x;
        As[ac + 1][ar] = av.y;
        As[ac + 2][ar] = av.z;
        As[ac + 3][ar] = av.w;
        float4 bv = *(const float4*)(Bptr + (size_t)k0 * N);
        *(float4*)&Bs[br][bc] = bv;
        __syncthreads();

        #pragma unroll
        for (int k = 0; k < BKK; k++) {
            float a[8], b[8];
            *(float4*)&a[0] = *(const float4*)&As[k][ty * 4];
            *(float4*)&a[4] = *(const float4*)&As[k][ty * 4 + 64];
            *(float4*)&b[0] = *(const float4*)&Bs[k][tx * 4];
            *(float4*)&b[4] = *(const float4*)&Bs[k][tx * 4 + 64];
            #pragma unroll
            for (int i = 0; i < 8; i++)
                #pragma unroll
                for (int j = 0; j < 8; j++)
                    acc[i][j] += a[i] * b[j];
        }
        __syncthreads();
    }

    #pragma unroll
    for (int ih = 0; ih < 2; ih++) {
        #pragma unroll
        for (int i = 0; i < 4; i++) {
            const int r = row0 + ty * 4 + ih * 64 + i;
            #pragma unroll
            for (int jh = 0; jh < 2; jh++) {
                float4 o;
                o.x = alpha * acc[ih * 4 + i][jh * 4 + 0];
                o.y = alpha * acc[ih * 4 + i][jh * 4 + 1];
                o.z = alpha * acc[ih * 4 + i][jh * 4 + 2];
                o.w = alpha * acc[ih * 4 + i][jh * 4 + 3];
                *(float4*)&C[(size_t)r * N + col0 + tx * 4 + jh * 64] = o;
            }
        }
    }
}

// ---------------------------------------------------------------------------
// Differential flash attention + per-head LayerNorm.
// 512 threads = 16 warps; each warp owns one query row; 16 rows per block.
// Grid: (N/16, H, B).
// ---------------------------------------------------------------------------
#define KPAD 132   // 128 + 4 pad: row stride 528B (16B-aligned, conflict-free)

__global__ void __launch_bounds__(512)
attn_kernel(const float* __restrict__ ln_g, const float* __restrict__ ln_b) {
    __shared__ __align__(16) float sQ[16][128];
    __shared__ __align__(16) float sK[32][KPAD];
    __shared__ __align__(16) float sV[32][KPAD];

    const int tid  = threadIdx.x;
    const int warp = tid >> 5;
    const int lane = tid & 31;
    const int h  = blockIdx.y;
    const int b  = blockIdx.z;
    const int q0 = blockIdx.x * 16;

    const float* Qb = g_Q + (size_t)b * NN * EE + h * VDIM;
    const float* Kb = g_K + (size_t)b * NN * EE + h * VDIM;
    const float* Vb = g_V + (size_t)b * NN * EE + h * VDIM;

    // Q tile: 16 rows x 32 float4 = 512 loads, one per thread
    {
        int r = tid >> 5, c = (tid & 31) * 4;
        *(float4*)&sQ[r][c] = *(const float4*)&Qb[(size_t)(q0 + r) * EE + c];
    }

    float m0 = -1e30f, l0 = 0.f;
    float m1 = -1e30f, l1 = 0.f;
    float o0[4] = {0.f, 0.f, 0.f, 0.f};
    float o1[4] = {0.f, 0.f, 0.f, 0.f};

    for (int j0 = 0; j0 < NN; j0 += 32) {
        __syncthreads();
        // K/V tile: 32 rows x 32 float4 = 1024 float4, 2 per thread
        #pragma unroll
        for (int it = 0; it < 2; it++) {
            int idx = tid + it * 512;
            int j = idx >> 5, c = (idx & 31) * 4;
            *(float4*)&sK[j][c] = *(const float4*)&Kb[(size_t)(j0 + j) * EE + c];
            *(float4*)&sV[j][c] = *(const float4*)&Vb[(size_t)(j0 + j) * EE + c];
        }
        __syncthreads();

        // scores: lane owns key (j0+lane); branch0 dims [0,64), branch1 [64,128)
        float s0 = 0.f, s1 = 0.f;
        const float* qr = sQ[warp];
        const float* kr = sK[lane];
        #pragma unroll
        for (int dv = 0; dv < 16; dv++) {
            float4 q4 = *(const float4*)&qr[dv * 4];
            float4 k4 = *(const float4*)&kr[dv * 4];
            s0 += q4.x * k4.x + q4.y * k4.y + q4.z * k4.z + q4.w * k4.w;
        }
        #pragma unroll
        for (int dv = 16; dv < 32; dv++) {
            float4 q4 = *(const float4*)&qr[dv * 4];
            float4 k4 = *(const float4*)&kr[dv * 4];
            s1 += q4.x * k4.x + q4.y * k4.y + q4.z * k4.z + q4.w * k4.w;
        }

        // warp-wide online softmax update, both branches
        float t0 = s0, t1 = s1;
        #pragma unroll
        for (int off = 16; off; off >>= 1) {
            t0 = fmaxf(t0, __shfl_xor_sync(0xFFFFFFFFu, t0, off));
            t1 = fmaxf(t1, __shfl_xor_sync(0xFFFFFFFFu, t1, off));
        }
        float m0n = fmaxf(m0, t0), m1n = fmaxf(m1, t1);
        float c0 = __expf(m0 - m0n), c1 = __expf(m1 - m1n);
        float p0 = __expf(s0 - m0n), p1 = __expf(s1 - m1n);
        float ps0 = p0, ps1 = p1;
        #pragma unroll
        for (int off = 16; off; off >>= 1) {
            ps0 += __shfl_xor_sync(0xFFFFFFFFu, ps0, off);
            ps1 += __shfl_xor_sync(0xFFFFFFFFu, ps1, off);
        }
        l0 = l0 * c0 + ps0;
        l1 = l1 * c1 + ps1;
        m0 = m0n; m1 = m1n;
        #pragma unroll
        for (int cI = 0; cI < 4; cI++) { o0[cI] *= c0; o1[cI] *= c1; }

        // PV accumulate; lane owns dims d = lane + 32*cI (conflict-free)
        #pragma unroll 4
        for (int j = 0; j < 32; j++) {
            float pj0 = __shfl_sync(0xFFFFFFFFu, p0, j);
            float pj1 = __shfl_sync(0xFFFFFFFFu, p1, j);
            #pragma unroll
            for (int cI = 0; cI < 4; cI++) {
                float vv = sV[j][lane + 32 * cI];
                o0[cI] += pj0 * vv;
                o1[cI] += pj1 * vv;
            }
        }
    }

    // finalize: differential combine + LayerNorm over 128 channels
    float lam = g_lambda;
    float inv0 = 1.f / l0, inv1 = 1.f / l1;
    float od[4];
    #pragma unroll
    for (int cI = 0; cI < 4; cI++)
        od[cI] = o0[cI] * inv0 - lam * (o1[cI] * inv1);

    float s = od[0] + od[1] + od[2] + od[3];
    #pragma unroll
    for (int off = 16; off; off >>= 1)
        s += __shfl_xor_sync(0xFFFFFFFFu, s, off);
    float mu = s * (1.f / 128.f);

    float vs = 0.f;
    #pragma unroll
    for (int cI = 0; cI < 4; cI++) {
        float dd = od[cI] - mu;
        vs += dd * dd;
    }
    #pragma unroll
    for (int off = 16; off; off >>= 1)
        vs += __shfl_xor_sync(0xFFFFFFFFu, vs, off);
    float rstd = rsqrtf(vs * (1.f / 128.f) + LN_EPS);

    float* outp = g_ATT + ((size_t)b * NN + q0 + warp) * EE + h * VDIM;
    #pragma unroll
    for (int cI = 0; cI < 4; cI++) {
        int d = lane + 32 * cI;
        outp[d] = (od[cI] - mu) * rstd * __ldg(&ln_g[d]) + __ldg(&ln_b[d]);
    }
}

// ---------------------------------------------------------------------------
// Launch
// ---------------------------------------------------------------------------
extern "C" void kernel_launch(void* const* d_in, const int* in_sizes, int n_in,
                              void* d_out, int out_size) {
    const float* x    = (const float*)d_in[0];
    const float* Wq   = (const float*)d_in[1];
    const float* Wk   = (const float*)d_in[2];
    const float* Wv   = (const float*)d_in[3];
    const float* Wo   = (const float*)d_in[4];
    const float* lq1  = (const float*)d_in[5];
    const float* lk1  = (const float*)d_in[6];
    const float* lq2  = (const float*)d_in[7];
    const float* lk2  = (const float*)d_in[8];
    const float* ln_g = (const float*)d_in[9];
    const float* ln_b = (const float*)d_in[10];
    float* out = (float*)d_out;

    float *pQ, *pK, *pV, *pATT;
    cudaGetSymbolAddress((void**)&pQ,   g_Q);
    cudaGetSymbolAddress((void**)&pK,   g_K);
    cudaGetSymbolAddress((void**)&pV,   g_V);
    cudaGetSymbolAddress((void**)&pATT, g_ATT);

    const int M = BB * NN;           // 4096
    const int Nc = EE, Kc = EE;      // 1024
    dim3 ggrid(Nc / BN, M / BM);     // (8, 32)
    dim3 gblk(256);

    lambda_kernel<<<1, 32>>>(lq1, lk1, lq2, lk2);

    const float qscale = 0.125f;     // D^-0.5, D=64
    sgemm128<<<ggrid, gblk>>>(x, Wq, pQ, M, Nc, Kc, qscale);
    sgemm128<<<ggrid, gblk>>>(x, Wk, pK, M, Nc, Kc, 1.0f);
    sgemm128<<<ggrid, gblk>>>(x, Wv, pV, M, Nc, Kc, 1.0f);

    dim3 agrid(NN / 16, HH, BB);     // (128, 8, 2)
    attn_kernel<<<agrid, 512>>>(ln_g, ln_b);

    sgemm128<<<ggrid, gblk>>>(pATT, Wo, out, M, Nc, Kc, 1.0f);
}

// round 6
// speedup vs baseline: 2.1332x; 2.1332x over previous
#include <cuda_runtime.h>
#include <math.h>

// Problem constants
#define BB   2
#define NN   2048
#define EE   1024
#define HH   8
#define DDIM 64          // half-head dim
#define VDIM 128         // 2*D
#define DEPTH_C 12
#define LN_EPS 1e-5f

// ---------------------------------------------------------------------------
// Device scratch (static — allocation-free rule)
// ---------------------------------------------------------------------------
__device__ float g_Q[(size_t)BB * NN * EE];
__device__ float g_K[(size_t)BB * NN * EE];
__device__ float g_V[(size_t)BB * NN * EE];
__device__ float g_ATT[(size_t)BB * NN * EE];
__device__ float g_O[(size_t)BB * HH * NN * VDIM];           // attention out pre-LN
__device__ float g_S[(size_t)BB * 2 * HH * NN * NN];         // 536 MB scores
__device__ float g_lambda;

// ---------------------------------------------------------------------------
// Lambda scalar
// ---------------------------------------------------------------------------
__global__ void lambda_kernel(const float* __restrict__ lq1,
                              const float* __restrict__ lk1,
                              const float* __restrict__ lq2,
                              const float* __restrict__ lk2) {
    int lane = threadIdx.x;
    float s1 = 0.f, s2 = 0.f;
    for (int i = lane; i < DDIM; i += 32) {
        s1 += lq1[i] * lk1[i];
        s2 += lq2[i] * lk2[i];
    }
    #pragma unroll
    for (int off = 16; off; off >>= 1) {
        s1 += __shfl_xor_sync(0xFFFFFFFFu, s1, off);
        s2 += __shfl_xor_sync(0xFFFFFFFFu, s2, off);
    }
    if (lane == 0) {
        float lam_init = 0.8f - 0.6f * expf(-0.3f * (float)DEPTH_C);
        g_lambda = expf(s1) - expf(s2) + lam_init;
    }
}

// ---------------------------------------------------------------------------
// SGEMM NN: C[M,N] = alpha * A[M,K] @ B[K,N], 128x128x8 tiles, 8x8/thread.
// ---------------------------------------------------------------------------
#define BM 128
#define BN 128
#define BKK 8

__global__ void __launch_bounds__(256)
sgemm128(const float* __restrict__ A, const float* __restrict__ B,
         float* __restrict__ C, int M, int N, int K, float alpha) {
    __shared__ __align__(16) float As[BKK][BM + 4];
    __shared__ __align__(16) float Bs[BKK][BN];

    const int tid = threadIdx.x;
    const int tx = tid & 15;
    const int ty = tid >> 4;
    const int row0 = blockIdx.y * BM;
    const int col0 = blockIdx.x * BN;

    const int ar = tid >> 1;
    const int ac = (tid & 1) * 4;
    const int br = tid >> 5;
    const int bc = (tid & 31) * 4;

    float acc[8][8];
    #pragma unroll
    for (int i = 0; i < 8; i++)
        #pragma unroll
        for (int j = 0; j < 8; j++) acc[i][j] = 0.f;

    const float* Aptr = A + (size_t)(row0 + ar) * K + ac;
    const float* Bptr = B + (size_t)br * N + col0 + bc;

    for (int k0 = 0; k0 < K; k0 += BKK) {
        float4 av = *(const float4*)(Aptr + k0);
        As[ac + 0][ar] = av.x;
        As[ac + 1][ar] = av.y;
        As[ac + 2][ar] = av.z;
        As[ac + 3][ar] = av.w;
        float4 bv = *(const float4*)(Bptr + (size_t)k0 * N);
        *(float4*)&Bs[br][bc] = bv;
        __syncthreads();

        #pragma unroll
        for (int k = 0; k < BKK; k++) {
            float a[8], b[8];
            *(float4*)&a[0] = *(const float4*)&As[k][ty * 4];
            *(float4*)&a[4] = *(const float4*)&As[k][ty * 4 + 64];
            *(float4*)&b[0] = *(const float4*)&Bs[k][tx * 4];
            *(float4*)&b[4] = *(const float4*)&Bs[k][tx * 4 + 64];
            #pragma unroll
            for (int i = 0; i < 8; i++)
                #pragma unroll
                for (int j = 0; j < 8; j++)
                    acc[i][j] += a[i] * b[j];
        }
        __syncthreads();
    }

    #pragma unroll
    for (int ih = 0; ih < 2; ih++)
        #pragma unroll
        for (int i = 0; i < 4; i++) {
            const int r = row0 + ty * 4 + ih * 64 + i;
            #pragma unroll
            for (int jh = 0; jh < 2; jh++) {
                float4 o;
                o.x = alpha * acc[ih * 4 + i][jh * 4 + 0];
                o.y = alpha * acc[ih * 4 + i][jh * 4 + 1];
                o.z = alpha * acc[ih * 4 + i][jh * 4 + 2];
                o.w = alpha * acc[ih * 4 + i][jh * 4 + 3];
                *(float4*)&C[(size_t)r * N + col0 + tx * 4 + jh * 64] = o;
            }
        }
}

// ---------------------------------------------------------------------------
// Scores GEMM (NT, batched): S[z][q][j] = Q[z,q,:64] . K[z,j,:64]
// z = b*16 + hh (half-head). Q/K rows have stride EE, channel offset hh*64.
// ---------------------------------------------------------------------------
__global__ void __launch_bounds__(256)
scores_gemm(const float* __restrict__ Qg, const float* __restrict__ Kg,
            float* __restrict__ S) {
    __shared__ __align__(16) float As[BKK][BM + 4];
    __shared__ __align__(16) float Bs[BKK][BM + 4];

    const int tid = threadIdx.x;
    const int tx = tid & 15;
    const int ty = tid >> 4;
    const int z  = blockIdx.z;              // 0..31
    const int b  = z >> 4;
    const int hh = z & 15;
    const int row0 = blockIdx.y * BM;       // q tile
    const int col0 = blockIdx.x * BM;       // j tile

    const int ar = tid >> 1;
    const int ac = (tid & 1) * 4;

    const float* Qp = Qg + (size_t)b * NN * EE + hh * DDIM + (size_t)(row0 + ar) * EE + ac;
    const float* Kp = Kg + (size_t)b * NN * EE + hh * DDIM + (size_t)(col0 + ar) * EE + ac;

    float acc[8][8];
    #pragma unroll
    for (int i = 0; i < 8; i++)
        #pragma unroll
        for (int j = 0; j < 8; j++) acc[i][j] = 0.f;

    #pragma unroll
    for (int k0 = 0; k0 < DDIM; k0 += BKK) {
        float4 av = *(const float4*)(Qp + k0);
        As[ac + 0][ar] = av.x;
        As[ac + 1][ar] = av.y;
        As[ac + 2][ar] = av.z;
        As[ac + 3][ar] = av.w;
        float4 bv = *(const float4*)(Kp + k0);
        Bs[ac + 0][ar] = bv.x;
        Bs[ac + 1][ar] = bv.y;
        Bs[ac + 2][ar] = bv.z;
        Bs[ac + 3][ar] = bv.w;
        __syncthreads();

        #pragma unroll
        for (int k = 0; k < BKK; k++) {
            float a[8], b2[8];
            *(float4*)&a[0]  = *(const float4*)&As[k][ty * 4];
            *(float4*)&a[4]  = *(const float4*)&As[k][ty * 4 + 64];
            *(float4*)&b2[0] = *(const float4*)&Bs[k][tx * 4];
            *(float4*)&b2[4] = *(const float4*)&Bs[k][tx * 4 + 64];
            #pragma unroll
            for (int i = 0; i < 8; i++)
                #pragma unroll
                for (int j = 0; j < 8; j++)
                    acc[i][j] += a[i] * b2[j];
        }
        __syncthreads();
    }

    float* Cp = S + (size_t)z * NN * NN;
    #pragma unroll
    for (int ih = 0; ih < 2; ih++)
        #pragma unroll
        for (int i = 0; i < 4; i++) {
            const int r = row0 + ty * 4 + ih * 64 + i;
            #pragma unroll
            for (int jh = 0; jh < 2; jh++) {
                float4 o;
                o.x = acc[ih * 4 + i][jh * 4 + 0];
                o.y = acc[ih * 4 + i][jh * 4 + 1];
                o.z = acc[ih * 4 + i][jh * 4 + 2];
                o.w = acc[ih * 4 + i][jh * 4 + 3];
                *(float4*)&Cp[(size_t)r * NN + col0 + tx * 4 + jh * 64] = o;
            }
        }
}

// ---------------------------------------------------------------------------
// Softmax + differential combine, in place.
// One 256-thread block per (b,h,q). w = softmax(S0) - lam*softmax(S1) -> S0.
// ---------------------------------------------------------------------------
__device__ __forceinline__ float2 block_reduce2(float2 v, bool do_max,
                                                float2* red) {
    #pragma unroll
    for (int off = 16; off; off >>= 1) {
        float ox = __shfl_xor_sync(0xFFFFFFFFu, v.x, off);
        float oy = __shfl_xor_sync(0xFFFFFFFFu, v.y, off);
        if (do_max) { v.x = fmaxf(v.x, ox); v.y = fmaxf(v.y, oy); }
        else        { v.x += ox;            v.y += oy; }
    }
    int warp = threadIdx.x >> 5, lane = threadIdx.x & 31;
    if (lane == 0) red[warp] = v;
    __syncthreads();
    if (warp == 0) {
        float2 t = (lane < 8) ? red[lane]
                              : (do_max ? make_float2(-1e30f, -1e30f)
                                        : make_float2(0.f, 0.f));
        #pragma unroll
        for (int off = 4; off; off >>= 1) {
            float ox = __shfl_xor_sync(0xFFFFFFFFu, t.x, off);
            float oy = __shfl_xor_sync(0xFFFFFFFFu, t.y, off);
            if (do_max) { t.x = fmaxf(t.x, ox); t.y = fmaxf(t.y, oy); }
            else        { t.x += ox;            t.y += oy; }
        }
        if (lane == 0) red[0] = t;
    }
    __syncthreads();
    float2 r = red[0];
    __syncthreads();
    return r;
}

__global__ void __launch_bounds__(256)
softmax_diff(float* __restrict__ S) {
    __shared__ float2 red[8];

    const int gid = blockIdx.x;                // 0 .. B*H*N-1
    const int b = gid >> 14;                   // /(8*2048)
    const int h = (gid >> 11) & 7;
    const int q = gid & 2047;

    float* s0 = S + ((size_t)(b * 16 + 2 * h)     * NN + q) * NN;
    float* s1 = S + ((size_t)(b * 16 + 2 * h + 1) * NN + q) * NN;

    const int tid = threadIdx.x;
    float v0[8], v1[8];
    *(float4*)&v0[0] = *(const float4*)&s0[tid * 4];
    *(float4*)&v0[4] = *(const float4*)&s0[tid * 4 + 1024];
    *(float4*)&v1[0] = *(const float4*)&s1[tid * 4];
    *(float4*)&v1[4] = *(const float4*)&s1[tid * 4 + 1024];

    float2 mx = make_float2(-1e30f, -1e30f);
    #pragma unroll
    for (int i = 0; i < 8; i++) {
        mx.x = fmaxf(mx.x, v0[i]);
        mx.y = fmaxf(mx.y, v1[i]);
    }
    mx = block_reduce2(mx, true, red);

    float2 sm = make_float2(0.f, 0.f);
    #pragma unroll
    for (int i = 0; i < 8; i++) {
        v0[i] = __expf(v0[i] - mx.x);
        v1[i] = __expf(v1[i] - mx.y);
        sm.x += v0[i];
        sm.y += v1[i];
    }
    sm = block_reduce2(sm, false, red);

    const float lam  = g_lambda;
    const float inv0 = 1.f / sm.x;
    const float inv1 = lam / sm.y;
    float w[8];
    #pragma unroll
    for (int i = 0; i < 8; i++)
        w[i] = v0[i] * inv0 - v1[i] * inv1;

    *(float4*)&s0[tid * 4]        = *(float4*)&w[0];
    *(float4*)&s0[tid * 4 + 1024] = *(float4*)&w[4];
}

// ---------------------------------------------------------------------------
// PV GEMM (batched, strided): O[z][q][d] = sum_j W[z][q][j] * V[b,j,h*128+d]
// ---------------------------------------------------------------------------
__global__ void __launch_bounds__(256)
pv_gemm(const float* __restrict__ S, const float* __restrict__ Vg,
        float* __restrict__ O) {
    __shared__ __align__(16) float As[BKK][BM + 4];
    __shared__ __align__(16) float Bs[BKK][BN];

    const int tid = threadIdx.x;
    const int tx = tid & 15;
    const int ty = tid >> 4;
    const int z = blockIdx.z;           // 0..15
    const int b = z >> 3;
    const int h = z & 7;
    const int row0 = blockIdx.y * BM;

    const int ar = tid >> 1;
    const int ac = (tid & 1) * 4;
    const int br = tid >> 5;
    const int bc = (tid & 31) * 4;

    const float* Ap = S + (size_t)(b * 16 + 2 * h) * NN * NN + (size_t)(row0 + ar) * NN + ac;
    const float* Bp = Vg + (size_t)b * NN * EE + h * VDIM + (size_t)br * EE + bc;

    float acc[8][8];
    #pragma unroll
    for (int i = 0; i < 8; i++)
        #pragma unroll
        for (int j = 0; j < 8; j++) acc[i][j] = 0.f;

    for (int k0 = 0; k0 < NN; k0 += BKK) {
        float4 av = *(const float4*)(Ap + k0);
        As[ac + 0][ar] = av.x;
        As[ac + 1][ar] = av.y;
        As[ac + 2][ar] = av.z;
        As[ac + 3][ar] = av.w;
        float4 bv = *(const float4*)(Bp + (size_t)k0 * EE);
        *(float4*)&Bs[br][bc] = bv;
        __syncthreads();

        #pragma unroll
        for (int k = 0; k < BKK; k++) {
            float a[8], b2[8];
            *(float4*)&a[0]  = *(const float4*)&As[k][ty * 4];
            *(float4*)&a[4]  = *(const float4*)&As[k][ty * 4 + 64];
            *(float4*)&b2[0] = *(const float4*)&Bs[k][tx * 4];
            *(float4*)&b2[4] = *(const float4*)&Bs[k][tx * 4 + 64];
            #pragma unroll
            for (int i = 0; i < 8; i++)
                #pragma unroll
                for (int j = 0; j < 8; j++)
                    acc[i][j] += a[i] * b2[j];
        }
        __syncthreads();
    }

    float* Cp = O + (size_t)z * NN * VDIM;
    #pragma unroll
    for (int ih = 0; ih < 2; ih++)
        #pragma unroll
        for (int i = 0; i < 4; i++) {
            const int r = row0 + ty * 4 + ih * 64 + i;
            #pragma unroll
            for (int jh = 0; jh < 2; jh++) {
                float4 o;
                o.x = acc[ih * 4 + i][jh * 4 + 0];
                o.y = acc[ih * 4 + i][jh * 4 + 1];
                o.z = acc[ih * 4 + i][jh * 4 + 2];
                o.w = acc[ih * 4 + i][jh * 4 + 3];
                *(float4*)&Cp[(size_t)r * VDIM + tx * 4 + jh * 64] = o;
            }
        }
}

// ---------------------------------------------------------------------------
// Per-head LayerNorm over 128 channels; warp per row.
// ---------------------------------------------------------------------------
__global__ void __launch_bounds__(256)
ln_kernel(const float* __restrict__ O, float* __restrict__ ATT,
          const float* __restrict__ ln_g, const float* __restrict__ ln_b) {
    const int warp = threadIdx.x >> 5;
    const int lane = threadIdx.x & 31;
    const int idx = blockIdx.x * 8 + warp;     // row id: z*2048 + n
    const int z = idx >> 11;
    const int n = idx & 2047;
    const int b = z >> 3;
    const int h = z & 7;

    float4 v = *(const float4*)&O[(size_t)idx * VDIM + lane * 4];

    float s = v.x + v.y + v.z + v.w;
    #pragma unroll
    for (int off = 16; off; off >>= 1)
        s += __shfl_xor_sync(0xFFFFFFFFu, s, off);
    float mu = s * (1.f / 128.f);

    float dx = v.x - mu, dy = v.y - mu, dz = v.z - mu, dw = v.w - mu;
    float vs = dx * dx + dy * dy + dz * dz + dw * dw;
    #pragma unroll
    for (int off = 16; off; off >>= 1)
        vs += __shfl_xor_sync(0xFFFFFFFFu, vs, off);
    float rstd = rsqrtf(vs * (1.f / 128.f) + LN_EPS);

    float4 g = *(const float4*)&ln_g[lane * 4];
    float4 be = *(const float4*)&ln_b[lane * 4];
    float4 o;
    o.x = dx * rstd * g.x + be.x;
    o.y = dy * rstd * g.y + be.y;
    o.z = dz * rstd * g.z + be.z;
    o.w = dw * rstd * g.w + be.w;
    *(float4*)&ATT[((size_t)b * NN + n) * EE + h * VDIM + lane * 4] = o;
}

// ---------------------------------------------------------------------------
// Launch
// ---------------------------------------------------------------------------
extern "C" void kernel_launch(void* const* d_in, const int* in_sizes, int n_in,
                              void* d_out, int out_size) {
    const float* x    = (const float*)d_in[0];
    const float* Wq   = (const float*)d_in[1];
    const float* Wk   = (const float*)d_in[2];
    const float* Wv   = (const float*)d_in[3];
    const float* Wo   = (const float*)d_in[4];
    const float* lq1  = (const float*)d_in[5];
    const float* lk1  = (const float*)d_in[6];
    const float* lq2  = (const float*)d_in[7];
    const float* lk2  = (const float*)d_in[8];
    const float* ln_g = (const float*)d_in[9];
    const float* ln_b = (const float*)d_in[10];
    float* out = (float*)d_out;

    float *pQ, *pK, *pV, *pATT, *pO, *pS;
    cudaGetSymbolAddress((void**)&pQ,   g_Q);
    cudaGetSymbolAddress((void**)&pK,   g_K);
    cudaGetSymbolAddress((void**)&pV,   g_V);
    cudaGetSymbolAddress((void**)&pATT, g_ATT);
    cudaGetSymbolAddress((void**)&pO,   g_O);
    cudaGetSymbolAddress((void**)&pS,   g_S);

    const int M = BB * NN;           // 4096
    const int Nc = EE, Kc = EE;      // 1024
    dim3 ggrid(Nc / BN, M / BM);     // (8, 32)

    lambda_kernel<<<1, 32>>>(lq1, lk1, lq2, lk2);

    const float qscale = 0.125f;     // D^-0.5
    sgemm128<<<ggrid, 256>>>(x, Wq, pQ, M, Nc, Kc, qscale);
    sgemm128<<<ggrid, 256>>>(x, Wk, pK, M, Nc, Kc, 1.0f);
    sgemm128<<<ggrid, 256>>>(x, Wv, pV, M, Nc, Kc, 1.0f);

    dim3 sgrid(NN / BM, NN / BM, BB * 2 * HH);   // (16,16,32)
    scores_gemm<<<sgrid, 256>>>(pQ, pK, pS);

    softmax_diff<<<BB * HH * NN, 256>>>(pS);

    dim3 pvgrid(1, NN / BM, BB * HH);            // (1,16,16)
    pv_gemm<<<pvgrid, 256>>>(pS, pV, pO);

    ln_kernel<<<BB * HH * NN / 8, 256>>>(pO, pATT, ln_g, ln_b);

    sgemm128<<<ggrid, 256>>>(pATT, Wo, out, M, Nc, Kc, 1.0f);
}